// round 6
// baseline (speedup 1.0000x reference)
#include <cuda_runtime.h>
#include <cstdint>

#define BB 8
#define CC 512
#define DD 64
#define NN 16384
#define PARAM 10.0f
#define EPS 1e-6f

__device__ float g_Q[BB*DD*NN];        // phi(Q) [b][m][n]
__device__ float g_Ksum[BB*DD];
__device__ float g_P[BB*128*CC*DD];    // partial KX^T [b][ntile][c][m]
__device__ float g_KXT[BB*CC*DD];      // (phiK @ x^T)^T [b][c][m]
__device__ float g_KVT[BB*CC*DD];      // KV^T (no bias) [b][c][m]

__device__ __forceinline__ float fmap(float t) {
    return t > 0.f ? fmaf(PARAM, t, 1.f) : __expf(PARAM * t);
}
__device__ __forceinline__ uint32_t tf(float x) {
    uint32_t u; asm("cvt.rna.tf32.f32 %0, %1;" : "=r"(u) : "f"(x)); return u;
}
#define MMA8(d, a, b0, b1) \
    asm volatile("mma.sync.aligned.m16n8k8.row.col.f32.tf32.tf32.f32 " \
        "{%0,%1,%2,%3}, {%4,%5,%6,%7}, {%8,%9}, {%0,%1,%2,%3};" \
        : "+f"((d)[0]), "+f"((d)[1]), "+f"((d)[2]), "+f"((d)[3]) \
        : "r"((a)[0]), "r"((a)[1]), "r"((a)[2]), "r"((a)[3]), "r"(b0), "r"(b1))

// ---------------------------------------------------------------------------
__global__ void k_zero() {
    int i = blockIdx.x*blockDim.x + threadIdx.x;
    if (i < BB*CC*DD) g_KVT[i] = 0.f;
    if (i < BB*DD) g_Ksum[i] = 0.f;
}

// ---------------------------------------------------------------------------
// k_qkx: fused projection + KX.
// Phase 1: C[128m][128n] = [Wq;Wk] @ x_tile (tf32 mma, k=512).
//          m<64 -> fmap -> g_Q; m>=64 -> fmap -> smem KtS[n][m] + Ksum atomics.
// Phase 2: KX partial[c][m] = x[c][n-tile] @ phiK^T, plain stores to g_P slot.
// Smem union (47.1KB static):
//   phase1: As [128][36] @0, Bs [32][136] @4608 (words)
//   phase2: As2 [128][20] @0, KtS [128][72] @2560 (words)
// ---------------------------------------------------------------------------
__global__ __launch_bounds__(256) void k_qkx(const float* __restrict__ x,
        const float* __restrict__ Wq, const float* __restrict__ bq,
        const float* __restrict__ Wk, const float* __restrict__ bk) {
    __shared__ __align__(16) uint32_t S[11776];
    uint32_t* As = S;            // [128][36]
    uint32_t* Bs = S + 4608;     // [32][136]
    uint32_t* Kt = S + 2560;     // [128][72]
    const int tid = threadIdx.x, w = tid>>5, lane = tid&31;
    const int gr = lane>>2, qt = lane&3;
    const int b = blockIdx.y, n0 = blockIdx.x*128;
    const int M0 = (w>>1)*32, N0 = (w&1)*64;      // phase-1 warp tile
    const int M2 = (w>>1)*32, N2 = (w&1)*32;      // phase-2 warp tile
    const float* xb = x + (size_t)b*CC*NN;

    // ================= Phase 1: projection =================
    float4 pA[4], pB[4];
    #pragma unroll
    for (int i = 0; i < 4; i++) {
        int id = tid + i*256, r = id>>3, c4 = id&7;
        const float* Wr = r < 64 ? Wq + r*CC : Wk + (size_t)(r-64)*CC;
        pA[i] = *(const float4*)(Wr + c4*4);
    }
    #pragma unroll
    for (int i = 0; i < 4; i++) {
        int id = tid + i*256, r = id>>5, n4 = id&31;
        pB[i] = *(const float4*)(xb + (size_t)r*NN + n0 + n4*4);
    }
    float acc[2][8][4];
    #pragma unroll
    for (int mt = 0; mt < 2; mt++)
        #pragma unroll
        for (int nt = 0; nt < 8; nt++)
            #pragma unroll
            for (int i = 0; i < 4; i++) acc[mt][nt][i] = 0.f;

    for (int ci = 0; ci < 16; ci++) {
        #pragma unroll
        for (int i = 0; i < 4; i++) {
            int id = tid + i*256, r = id>>3, c4 = id&7;
            uint32_t* p = &As[r*36 + c4*4];
            p[0]=tf(pA[i].x); p[1]=tf(pA[i].y); p[2]=tf(pA[i].z); p[3]=tf(pA[i].w);
        }
        #pragma unroll
        for (int i = 0; i < 4; i++) {
            int id = tid + i*256, r = id>>5, n4 = id&31;
            uint32_t* p = &Bs[r*136 + n4*4];
            p[0]=tf(pB[i].x); p[1]=tf(pB[i].y); p[2]=tf(pB[i].z); p[3]=tf(pB[i].w);
        }
        __syncthreads();
        if (ci < 15) {
            int kc = (ci+1)*32;
            #pragma unroll
            for (int i = 0; i < 4; i++) {
                int id = tid + i*256, r = id>>3, c4 = id&7;
                const float* Wr = r < 64 ? Wq + r*CC : Wk + (size_t)(r-64)*CC;
                pA[i] = *(const float4*)(Wr + kc + c4*4);
            }
            #pragma unroll
            for (int i = 0; i < 4; i++) {
                int id = tid + i*256, r = id>>5, n4 = id&31;
                pB[i] = *(const float4*)(xb + (size_t)(kc+r)*NN + n0 + n4*4);
            }
        }
        #pragma unroll
        for (int k0 = 0; k0 < 32; k0 += 8) {
            uint32_t af[2][4], bf[8][2];
            #pragma unroll
            for (int mt = 0; mt < 2; mt++) {
                int base = (M0 + 16*mt + gr)*36 + k0 + qt;
                af[mt][0] = As[base];       af[mt][1] = As[base + 8*36];
                af[mt][2] = As[base + 4];   af[mt][3] = As[base + 8*36 + 4];
            }
            #pragma unroll
            for (int nt = 0; nt < 8; nt++) {
                int bb = (k0 + qt)*136 + N0 + 8*nt + gr;
                bf[nt][0] = Bs[bb]; bf[nt][1] = Bs[bb + 4*136];
            }
            #pragma unroll
            for (int mt = 0; mt < 2; mt++)
                #pragma unroll
                for (int nt = 0; nt < 8; nt++)
                    MMA8(acc[mt][nt], af[mt], bf[nt][0], bf[nt][1]);
        }
        __syncthreads();
    }

    // Epilogue: Q -> gmem, K -> smem KtS[n][m] (tf32) + Ksum
    #pragma unroll
    for (int mt = 0; mt < 2; mt++)
        #pragma unroll
        for (int h = 0; h < 2; h++) {
            const int m = M0 + 16*mt + 8*h + gr;
            const float bias = m < 64 ? __ldg(bq + m) : __ldg(bk + m - 64);
            float vv[8][2], ks = 0.f;
            #pragma unroll
            for (int nt = 0; nt < 8; nt++) {
                vv[nt][0] = fmap(acc[mt][nt][2*h]   + bias);
                vv[nt][1] = fmap(acc[mt][nt][2*h+1] + bias);
                ks += vv[nt][0] + vv[nt][1];
            }
            if (m < 64) {
                float* dst = g_Q + ((size_t)b*DD + m)*NN + n0 + N0;
                #pragma unroll
                for (int nt = 0; nt < 8; nt++)
                    *(float2*)(dst + 8*nt + 2*qt) = make_float2(vv[nt][0], vv[nt][1]);
            } else {
                const int mm = m - 64;
                #pragma unroll
                for (int nt = 0; nt < 8; nt++) {
                    int nl = N0 + 8*nt + 2*qt;
                    Kt[nl*72 + mm]     = tf(vv[nt][0]);
                    Kt[(nl+1)*72 + mm] = tf(vv[nt][1]);
                }
                ks += __shfl_xor_sync(0xffffffffu, ks, 1);
                ks += __shfl_xor_sync(0xffffffffu, ks, 2);
                if (qt == 0) atomicAdd(&g_Ksum[b*DD + mm], ks);
            }
        }
    __syncthreads();

    // ================= Phase 2: KX partial =================
    float acc2[2][4][4];
    #pragma unroll
    for (int mt = 0; mt < 2; mt++)
        #pragma unroll
        for (int nt = 0; nt < 4; nt++)
            #pragma unroll
            for (int i = 0; i < 4; i++) acc2[mt][nt][i] = 0.f;

    float4 pX[2];
    #pragma unroll
    for (int i = 0; i < 2; i++) {
        int id = tid + i*256, r = id>>2, n4 = id&3;
        pX[i] = *(const float4*)(xb + (size_t)r*NN + n0 + n4*4);
    }
    for (int it = 0; it < 32; it++) {     // cc = it>>3 (c-chunk), sub = it&7 (16-n)
        const int cc = it >> 3, sub = it & 7;
        #pragma unroll
        for (int i = 0; i < 2; i++) {
            int id = tid + i*256, r = id>>2, n4 = id&3;
            uint32_t* p = &S[r*20 + n4*4];
            p[0]=tf(pX[i].x); p[1]=tf(pX[i].y); p[2]=tf(pX[i].z); p[3]=tf(pX[i].w);
        }
        __syncthreads();
        if (it < 31) {
            int it2 = it + 1, cb2 = (it2>>3)*128, ng2 = n0 + (it2&7)*16;
            #pragma unroll
            for (int i = 0; i < 2; i++) {
                int id = tid + i*256, r = id>>2, n4 = id&3;
                pX[i] = *(const float4*)(xb + (size_t)(cb2 + r)*NN + ng2 + n4*4);
            }
        }
        #pragma unroll
        for (int k0 = 0; k0 < 16; k0 += 8) {
            uint32_t af[2][4], bf[4][2];
            #pragma unroll
            for (int mt = 0; mt < 2; mt++) {
                int base = (M2 + 16*mt + gr)*20 + k0 + qt;
                af[mt][0] = S[base];     af[mt][1] = S[base + 8*20];
                af[mt][2] = S[base + 4]; af[mt][3] = S[base + 8*20 + 4];
            }
            #pragma unroll
            for (int nt = 0; nt < 4; nt++) {
                int bb = (sub*16 + k0 + qt)*72 + N2 + 8*nt + gr;
                bf[nt][0] = Kt[bb]; bf[nt][1] = Kt[bb + 4*72];
            }
            #pragma unroll
            for (int mt = 0; mt < 2; mt++)
                #pragma unroll
                for (int nt = 0; nt < 4; nt++)
                    MMA8(acc2[mt][nt], af[mt], bf[nt][0], bf[nt][1]);
        }
        __syncthreads();
        if (sub == 7) {
            float* Pb = g_P + (((size_t)b*128 + blockIdx.x)*CC + cc*128)*DD;
            #pragma unroll
            for (int mt = 0; mt < 2; mt++)
                #pragma unroll
                for (int h = 0; h < 2; h++) {
                    int cl = M2 + 16*mt + 8*h + gr;
                    #pragma unroll
                    for (int nt = 0; nt < 4; nt++) {
                        int m = N2 + 8*nt + 2*qt;
                        *(float2*)(Pb + cl*DD + m) =
                            make_float2(acc2[mt][nt][2*h], acc2[mt][nt][2*h+1]);
                    }
                }
            #pragma unroll
            for (int mt = 0; mt < 2; mt++)
                #pragma unroll
                for (int nt = 0; nt < 4; nt++)
                    #pragma unroll
                    for (int i = 0; i < 4; i++) acc2[mt][nt][i] = 0.f;
        }
    }
}

// ---------------------------------------------------------------------------
// k_red: g_KXT[b][c][m] = sum over 128 n-tiles of g_P
// ---------------------------------------------------------------------------
__global__ __launch_bounds__(256) void k_red() {
    const int i = blockIdx.x*256 + threadIdx.x;   // < BB*CC*DD
    const int b = i >> 15, cm = i & 32767;
    const float* p = g_P + ((size_t)b << 22) + cm;
    float s0=0.f, s1=0.f, s2=0.f, s3=0.f;
    #pragma unroll 8
    for (int t = 0; t < 128; t += 4) {
        s0 += p[(size_t)(t+0) << 15];
        s1 += p[(size_t)(t+1) << 15];
        s2 += p[(size_t)(t+2) << 15];
        s3 += p[(size_t)(t+3) << 15];
    }
    g_KXT[i] = (s0 + s1) + (s2 + s3);
}

// ---------------------------------------------------------------------------
// k_kv (SIMT, split-K=4): KVT[c][m] += sum_{c'} Wv[c][c'] * KXT[c'][m]
// ---------------------------------------------------------------------------
__global__ __launch_bounds__(256) void k_kv(const float* __restrict__ Wv) {
    __shared__ float Ws[64*36];   // [c][c'(32)+4]
    __shared__ float Xs[32*68];   // [c'][m(64)+4]
    const int c0 = blockIdx.x*64, sp = blockIdx.y, b = blockIdx.z;
    const int tid = threadIdx.x, tx = tid&15, ty = tid>>4;

    float acc[4][4] = {};
    for (int kk = 0; kk < 4; kk++) {
        const int cp0 = sp*128 + kk*32;
        #pragma unroll
        for (int i = 0; i < 2; i++) {
            int id = tid + i*256, r = id>>3, q4 = id&7;
            *(float4*)&Ws[r*36 + q4*4] =
                *(const float4*)(Wv + (size_t)(c0 + r)*CC + cp0 + q4*4);
        }
        #pragma unroll
        for (int i = 0; i < 2; i++) {
            int id = tid + i*256, r = id>>4, m4 = id&15;
            *(float4*)&Xs[r*68 + m4*4] =
                *(const float4*)(g_KXT + ((size_t)(b*CC) + cp0 + r)*DD + m4*4);
        }
        __syncthreads();
        #pragma unroll
        for (int k = 0; k < 32; k++) {
            float a[4], bb[4];
            #pragma unroll
            for (int i = 0; i < 4; i++) a[i] = Ws[(ty*4+i)*36 + k];
            #pragma unroll
            for (int j = 0; j < 4; j++) bb[j] = Xs[k*68 + tx*4 + j];
            #pragma unroll
            for (int i = 0; i < 4; i++)
                #pragma unroll
                for (int j = 0; j < 4; j++)
                    acc[i][j] = fmaf(a[i], bb[j], acc[i][j]);
        }
        __syncthreads();
    }
    #pragma unroll
    for (int i = 0; i < 4; i++)
        #pragma unroll
        for (int j = 0; j < 4; j++)
            atomicAdd(&g_KVT[((size_t)b*CC + c0 + ty*4+i)*DD + tx*4 + j], acc[i][j]);
}

// ---------------------------------------------------------------------------
// k_out: C[64c][64n] = (KVT+bv*Ksum)[c][m] @ phiQ[m][n]; fused den + residual.
// ---------------------------------------------------------------------------
__global__ __launch_bounds__(256) void k_out(const float* __restrict__ x,
        const float* __restrict__ bv, const float* __restrict__ gamma,
        float* __restrict__ out) {
    __shared__ uint32_t As[64*68];   // [c][m(64)+4]
    __shared__ uint32_t Bs[64*72];   // [m][n(64)+8]
    __shared__ float dens[64], kss[64];
    const int tid = threadIdx.x, w = tid>>5, lane = tid&31;
    const int gr = lane>>2, qt = lane&3;
    const int c0 = blockIdx.x*64, n0 = blockIdx.y*64, b = blockIdx.z;
    const int M0 = (w>>1)*16, N0 = (w&1)*32;

    if (tid < 64) kss[tid] = g_Ksum[b*DD + tid];
    #pragma unroll
    for (int i = 0; i < 4; i++) {     // A = KVT + bv*Ksum
        int id = tid + i*256, r = id>>4, m4 = id&15;
        float4 v = *(const float4*)(g_KVT + ((size_t)b*CC + c0 + r)*DD + m4*4);
        float4 k4 = *(const float4*)(g_Ksum + b*DD + m4*4);
        float bvc = __ldg(bv + c0 + r);
        v.x = fmaf(bvc, k4.x, v.x); v.y = fmaf(bvc, k4.y, v.y);
        v.z = fmaf(bvc, k4.z, v.z); v.w = fmaf(bvc, k4.w, v.w);
        uint32_t* p = &As[r*68 + m4*4];
        p[0]=tf(v.x); p[1]=tf(v.y); p[2]=tf(v.z); p[3]=tf(v.w);
    }
    #pragma unroll
    for (int i = 0; i < 4; i++) {     // B = phiQ [m][n]
        int id = tid + i*256, r = id>>4, n4 = id&15;
        float4 v = *(const float4*)(g_Q + ((size_t)b*DD + r)*NN + n0 + n4*4);
        uint32_t* p = &Bs[r*72 + n4*4];
        p[0]=tf(v.x); p[1]=tf(v.y); p[2]=tf(v.z); p[3]=tf(v.w);
    }
    __syncthreads();
    if (tid < 64) {                   // den[n] = sum_m phiQ*(Ksum+eps)
        float d = 0.f;
        #pragma unroll 16
        for (int m = 0; m < 64; m++)
            d = fmaf(__uint_as_float(Bs[m*72 + tid]), kss[m] + EPS, d);
        dens[tid] = d;
    }
    float acc[4][4];
    #pragma unroll
    for (int nt = 0; nt < 4; nt++)
        #pragma unroll
        for (int i = 0; i < 4; i++) acc[nt][i] = 0.f;
    #pragma unroll
    for (int k0 = 0; k0 < 64; k0 += 8) {
        uint32_t af[4], bf[4][2];
        int base = (M0 + gr)*68 + k0 + qt;
        af[0] = As[base];     af[1] = As[base + 8*68];
        af[2] = As[base + 4]; af[3] = As[base + 8*68 + 4];
        #pragma unroll
        for (int nt = 0; nt < 4; nt++) {
            int bb = (k0 + qt)*72 + N0 + 8*nt + gr;
            bf[nt][0] = Bs[bb]; bf[nt][1] = Bs[bb + 4*72];
        }
        #pragma unroll
        for (int nt = 0; nt < 4; nt++)
            MMA8(acc[nt], af, bf[nt][0], bf[nt][1]);
    }
    __syncthreads();
    const float gm = gamma[0];
    #pragma unroll
    for (int h = 0; h < 2; h++) {
        const int c = c0 + M0 + 8*h + gr;
        #pragma unroll
        for (int nt = 0; nt < 4; nt++) {
            const int nl = N0 + 8*nt + 2*qt;
            const float rn0 = gm / dens[nl], rn1 = gm / dens[nl+1];
            const size_t bi = ((size_t)b*CC + c)*NN + n0 + nl;
            float2 xv = *(const float2*)(x + bi);
            float2 o;
            o.x = fmaf(acc[nt][2*h],   rn0, xv.x);
            o.y = fmaf(acc[nt][2*h+1], rn1, xv.y);
            *(float2*)(out + bi) = o;
        }
    }
}

// ---------------------------------------------------------------------------
extern "C" void kernel_launch(void* const* d_in, const int* in_sizes, int n_in,
                              void* d_out, int out_size) {
    const float* x     = (const float*)d_in[0];
    const float* Wq    = (const float*)d_in[1];
    const float* bq    = (const float*)d_in[2];
    const float* Wk    = (const float*)d_in[3];
    const float* bk    = (const float*)d_in[4];
    const float* Wv    = (const float*)d_in[5];
    const float* bv    = (const float*)d_in[6];
    const float* gamma = (const float*)d_in[7];
    float* out = (float*)d_out;

    k_zero<<<512, 512>>>();
    k_qkx <<<dim3(NN/128, BB), 256>>>(x, Wq, bq, Wk, bk);
    k_red <<<BB*CC*DD/256, 256>>>();
    k_kv  <<<dim3(CC/64, 4, BB), 256>>>(Wv);
    k_out <<<dim3(CC/64, NN/64, BB), 256>>>(x, bv, gamma, out);
}

// round 7
// speedup vs baseline: 1.0577x; 1.0577x over previous
#include <cuda_runtime.h>
#include <cstdint>

#define BB 8
#define CC 512
#define DD 64
#define NN 16384
#define PARAM 10.0f
#define EPS 1e-6f
#define CDM (CC*DD)            // 32768
#define SLAB (BB*CC*DD)        // 262144

__device__ float g_Q[BB*DD*NN];      // phi(Q) [b][m][n]
__device__ float g_Kt[BB*NN*DD];     // phi(K) transposed [b][n][m]
__device__ float g_Ksum[BB*DD];
__device__ float g_P16[16*SLAB];     // KX^T partials [sp][b][c][m]
__device__ float g_KXT[SLAB];        // (phiK @ x^T)^T [b][c][m]
__device__ float g_KV4[4*SLAB];      // KV^T partials [sp][b][c][m]

__device__ __forceinline__ float fmap(float t) {
    return t > 0.f ? fmaf(PARAM, t, 1.f) : __expf(PARAM * t);
}
__device__ __forceinline__ uint32_t tf(float x) {
    uint32_t u; asm("cvt.rna.tf32.f32 %0, %1;" : "=r"(u) : "f"(x)); return u;
}
#define MMA8(d, a, b0, b1) \
    asm volatile("mma.sync.aligned.m16n8k8.row.col.f32.tf32.tf32.f32 " \
        "{%0,%1,%2,%3}, {%4,%5,%6,%7}, {%8,%9}, {%0,%1,%2,%3};" \
        : "+f"((d)[0]), "+f"((d)[1]), "+f"((d)[2]), "+f"((d)[3]) \
        : "r"((a)[0]), "r"((a)[1]), "r"((a)[2]), "r"((a)[3]), "r"(b0), "r"(b1))

// ---------------------------------------------------------------------------
__global__ void k_zero() {
    int i = threadIdx.x;
    if (i < BB*DD) g_Ksum[i] = 0.f;
}

// ---------------------------------------------------------------------------
// k_qk: C[128m][128n] = [Wq;Wk](128x512) @ x_tile(512c x 128n). tf32 mma.
// Epilogue: bias+fmap; m<64 -> g_Q[m][n]; m>=64 -> g_Kt[n][m], Ksum atomics.
// ---------------------------------------------------------------------------
__global__ __launch_bounds__(256) void k_qk(const float* __restrict__ x,
        const float* __restrict__ Wq, const float* __restrict__ bq,
        const float* __restrict__ Wk, const float* __restrict__ bk) {
    __shared__ uint32_t As[128*36];   // [m][k(32)+4]
    __shared__ uint32_t Bs[32*136];   // [k(c)][n(128)+8]
    const int tid = threadIdx.x, w = tid>>5, lane = tid&31;
    const int gr = lane>>2, qt = lane&3;
    const int b = blockIdx.y, n0 = blockIdx.x*128;
    const int M0 = (w>>1)*32, N0 = (w&1)*64;
    const float* xb = x + (size_t)b*CC*NN;

    float4 pA[4], pB[4];
    #pragma unroll
    for (int i = 0; i < 4; i++) {
        int id = tid + i*256, r = id>>3, c4 = id&7;
        const float* Wr = r < 64 ? Wq + r*CC : Wk + (size_t)(r-64)*CC;
        pA[i] = *(const float4*)(Wr + c4*4);
    }
    #pragma unroll
    for (int i = 0; i < 4; i++) {
        int id = tid + i*256, r = id>>5, n4 = id&31;
        pB[i] = *(const float4*)(xb + (size_t)r*NN + n0 + n4*4);
    }
    float acc[2][8][4];
    #pragma unroll
    for (int mt = 0; mt < 2; mt++)
        #pragma unroll
        for (int nt = 0; nt < 8; nt++)
            #pragma unroll
            for (int i = 0; i < 4; i++) acc[mt][nt][i] = 0.f;

    for (int ci = 0; ci < 16; ci++) {
        #pragma unroll
        for (int i = 0; i < 4; i++) {
            int id = tid + i*256, r = id>>3, c4 = id&7;
            uint32_t* p = &As[r*36 + c4*4];
            p[0]=tf(pA[i].x); p[1]=tf(pA[i].y); p[2]=tf(pA[i].z); p[3]=tf(pA[i].w);
        }
        #pragma unroll
        for (int i = 0; i < 4; i++) {
            int id = tid + i*256, r = id>>5, n4 = id&31;
            uint32_t* p = &Bs[r*136 + n4*4];
            p[0]=tf(pB[i].x); p[1]=tf(pB[i].y); p[2]=tf(pB[i].z); p[3]=tf(pB[i].w);
        }
        __syncthreads();
        if (ci < 15) {
            int kc = (ci+1)*32;
            #pragma unroll
            for (int i = 0; i < 4; i++) {
                int id = tid + i*256, r = id>>3, c4 = id&7;
                const float* Wr = r < 64 ? Wq + r*CC : Wk + (size_t)(r-64)*CC;
                pA[i] = *(const float4*)(Wr + kc + c4*4);
            }
            #pragma unroll
            for (int i = 0; i < 4; i++) {
                int id = tid + i*256, r = id>>5, n4 = id&31;
                pB[i] = *(const float4*)(xb + (size_t)(kc+r)*NN + n0 + n4*4);
            }
        }
        #pragma unroll
        for (int k0 = 0; k0 < 32; k0 += 8) {
            uint32_t af[2][4], bf[8][2];
            #pragma unroll
            for (int mt = 0; mt < 2; mt++) {
                int base = (M0 + 16*mt + gr)*36 + k0 + qt;
                af[mt][0] = As[base];       af[mt][1] = As[base + 8*36];
                af[mt][2] = As[base + 4];   af[mt][3] = As[base + 8*36 + 4];
            }
            #pragma unroll
            for (int nt = 0; nt < 8; nt++) {
                int bb = (k0 + qt)*136 + N0 + 8*nt + gr;
                bf[nt][0] = Bs[bb]; bf[nt][1] = Bs[bb + 4*136];
            }
            #pragma unroll
            for (int mt = 0; mt < 2; mt++)
                #pragma unroll
                for (int nt = 0; nt < 8; nt++)
                    MMA8(acc[mt][nt], af[mt], bf[nt][0], bf[nt][1]);
        }
        __syncthreads();
    }

    #pragma unroll
    for (int mt = 0; mt < 2; mt++)
        #pragma unroll
        for (int h = 0; h < 2; h++) {
            const int m = M0 + 16*mt + 8*h + gr;
            const float bias = m < 64 ? __ldg(bq + m) : __ldg(bk + m - 64);
            float vv[8][2], ks = 0.f;
            #pragma unroll
            for (int nt = 0; nt < 8; nt++) {
                vv[nt][0] = fmap(acc[mt][nt][2*h]   + bias);
                vv[nt][1] = fmap(acc[mt][nt][2*h+1] + bias);
                ks += vv[nt][0] + vv[nt][1];
            }
            if (m < 64) {
                float* dst = g_Q + ((size_t)b*DD + m)*NN + n0 + N0;
                #pragma unroll
                for (int nt = 0; nt < 8; nt++)
                    *(float2*)(dst + 8*nt + 2*qt) = make_float2(vv[nt][0], vv[nt][1]);
            } else {
                const int mm = m - 64;
                #pragma unroll
                for (int nt = 0; nt < 8; nt++) {
                    int n = n0 + N0 + 8*nt + 2*qt;
                    float* dk = g_Kt + ((size_t)b*NN + n)*DD + mm;
                    dk[0] = vv[nt][0]; dk[DD] = vv[nt][1];
                }
                ks += __shfl_xor_sync(0xffffffffu, ks, 1);
                ks += __shfl_xor_sync(0xffffffffu, ks, 2);
                if (qt == 0) atomicAdd(&g_Ksum[b*DD + mm], ks);
            }
        }
}

// ---------------------------------------------------------------------------
// k_kx: P16[sp][c][m] = x_tile(c x n-split) @ phiK^T. A=x, B=g_Kt. 16 splits,
// plain stores to private slot (no atomics).
// ---------------------------------------------------------------------------
__global__ __launch_bounds__(256) void k_kx(const float* __restrict__ x) {
    __shared__ uint32_t As[128*36];   // [c][k(32)+4]
    __shared__ uint32_t Bs[32*72];    // [k(n)][m(64)+8]
    const int tid = threadIdx.x, w = tid>>5, lane = tid&31;
    const int gr = lane>>2, qt = lane&3;
    const int c0 = blockIdx.x*128, b = blockIdx.z, sp = blockIdx.y;
    const int nbase = sp*(NN/16);
    const int M0 = (w>>1)*32, N0 = (w&1)*32;

    float4 pA[4], pB[2];
    #pragma unroll
    for (int i = 0; i < 4; i++) {
        int id = tid + i*256, r = id>>3, n4 = id&7;
        pA[i] = *(const float4*)(x + ((size_t)(b*CC + c0 + r))*NN + nbase + n4*4);
    }
    #pragma unroll
    for (int i = 0; i < 2; i++) {
        int id = tid + i*256, r = id>>4, m4 = id&15;
        pB[i] = *(const float4*)(g_Kt + ((size_t)b*NN + nbase + r)*DD + m4*4);
    }
    float acc[2][4][4];
    #pragma unroll
    for (int mt = 0; mt < 2; mt++)
        #pragma unroll
        for (int nt = 0; nt < 4; nt++)
            #pragma unroll
            for (int i = 0; i < 4; i++) acc[mt][nt][i] = 0.f;

    for (int ci = 0; ci < (NN/16)/32; ci++) {
        #pragma unroll
        for (int i = 0; i < 4; i++) {
            int id = tid + i*256, r = id>>3, n4 = id&7;
            uint32_t* p = &As[r*36 + n4*4];
            p[0]=tf(pA[i].x); p[1]=tf(pA[i].y); p[2]=tf(pA[i].z); p[3]=tf(pA[i].w);
        }
        #pragma unroll
        for (int i = 0; i < 2; i++) {
            int id = tid + i*256, r = id>>4, m4 = id&15;
            uint32_t* p = &Bs[r*72 + m4*4];
            p[0]=tf(pB[i].x); p[1]=tf(pB[i].y); p[2]=tf(pB[i].z); p[3]=tf(pB[i].w);
        }
        __syncthreads();
        if (ci < (NN/16)/32 - 1) {
            int kn = nbase + (ci+1)*32;
            #pragma unroll
            for (int i = 0; i < 4; i++) {
                int id = tid + i*256, r = id>>3, n4 = id&7;
                pA[i] = *(const float4*)(x + ((size_t)(b*CC + c0 + r))*NN + kn + n4*4);
            }
            #pragma unroll
            for (int i = 0; i < 2; i++) {
                int id = tid + i*256, r = id>>4, m4 = id&15;
                pB[i] = *(const float4*)(g_Kt + ((size_t)b*NN + kn + r)*DD + m4*4);
            }
        }
        #pragma unroll
        for (int k0 = 0; k0 < 32; k0 += 8) {
            uint32_t af[2][4], bf[4][2];
            #pragma unroll
            for (int mt = 0; mt < 2; mt++) {
                int base = (M0 + 16*mt + gr)*36 + k0 + qt;
                af[mt][0] = As[base];     af[mt][1] = As[base + 8*36];
                af[mt][2] = As[base + 4]; af[mt][3] = As[base + 8*36 + 4];
            }
            #pragma unroll
            for (int nt = 0; nt < 4; nt++) {
                int bb = (k0 + qt)*72 + N0 + 8*nt + gr;
                bf[nt][0] = Bs[bb]; bf[nt][1] = Bs[bb + 4*72];
            }
            #pragma unroll
            for (int mt = 0; mt < 2; mt++)
                #pragma unroll
                for (int nt = 0; nt < 4; nt++)
                    MMA8(acc[mt][nt], af[mt], bf[nt][0], bf[nt][1]);
        }
        __syncthreads();
    }
    float* Pb = g_P16 + (size_t)sp*SLAB + (size_t)b*CDM;
    #pragma unroll
    for (int mt = 0; mt < 2; mt++)
        #pragma unroll
        for (int h = 0; h < 2; h++) {
            int c = c0 + M0 + 16*mt + 8*h + gr;
            #pragma unroll
            for (int nt = 0; nt < 4; nt++) {
                int m = N0 + 8*nt + 2*qt;
                *(float2*)(Pb + (size_t)c*DD + m) =
                    make_float2(acc[mt][nt][2*h], acc[mt][nt][2*h+1]);
            }
        }
}

// ---------------------------------------------------------------------------
// k_red: g_KXT = sum over 16 slots of g_P16
// ---------------------------------------------------------------------------
__global__ __launch_bounds__(256) void k_red() {
    const int i = blockIdx.x*256 + threadIdx.x;   // < SLAB
    const float* p = g_P16 + i;
    float s0=0.f, s1=0.f, s2=0.f, s3=0.f;
    #pragma unroll
    for (int t = 0; t < 16; t += 4) {
        s0 += p[(size_t)(t+0)*SLAB];
        s1 += p[(size_t)(t+1)*SLAB];
        s2 += p[(size_t)(t+2)*SLAB];
        s3 += p[(size_t)(t+3)*SLAB];
    }
    g_KXT[i] = (s0 + s1) + (s2 + s3);
}

// ---------------------------------------------------------------------------
// k_kv (SIMT, 4 splits, slot stores): KV4[sp][c][m] = sum_{c' in split} Wv*KXT
// ---------------------------------------------------------------------------
__global__ __launch_bounds__(256) void k_kv(const float* __restrict__ Wv) {
    __shared__ float Ws[64*36];   // [c][c'(32)+4]
    __shared__ float Xs[32*68];   // [c'][m(64)+4]
    const int c0 = blockIdx.x*64, sp = blockIdx.y, b = blockIdx.z;
    const int tid = threadIdx.x, tx = tid&15, ty = tid>>4;

    float acc[4][4] = {};
    for (int kk = 0; kk < 4; kk++) {
        const int cp0 = sp*128 + kk*32;
        #pragma unroll
        for (int i = 0; i < 2; i++) {
            int id = tid + i*256, r = id>>3, q4 = id&7;
            *(float4*)&Ws[r*36 + q4*4] =
                *(const float4*)(Wv + (size_t)(c0 + r)*CC + cp0 + q4*4);
        }
        #pragma unroll
        for (int i = 0; i < 2; i++) {
            int id = tid + i*256, r = id>>4, m4 = id&15;
            *(float4*)&Xs[r*68 + m4*4] =
                *(const float4*)(g_KXT + ((size_t)(b*CC) + cp0 + r)*DD + m4*4);
        }
        __syncthreads();
        #pragma unroll
        for (int k = 0; k < 32; k++) {
            float a[4], bb[4];
            #pragma unroll
            for (int i = 0; i < 4; i++) a[i] = Ws[(ty*4+i)*36 + k];
            #pragma unroll
            for (int j = 0; j < 4; j++) bb[j] = Xs[k*68 + tx*4 + j];
            #pragma unroll
            for (int i = 0; i < 4; i++)
                #pragma unroll
                for (int j = 0; j < 4; j++)
                    acc[i][j] = fmaf(a[i], bb[j], acc[i][j]);
        }
        __syncthreads();
    }
    float* dst = g_KV4 + (size_t)sp*SLAB + ((size_t)b*CC + c0)*DD;
    #pragma unroll
    for (int i = 0; i < 4; i++)
        #pragma unroll
        for (int j = 0; j < 4; j++)
            dst[(size_t)(ty*4+i)*DD + tx*4 + j] = acc[i][j];
}

// ---------------------------------------------------------------------------
// k_out: C[64c][64n] = (sum KV4 + bv*Ksum)[c][m] @ phiQ[m][n]; fused den+resid.
// ---------------------------------------------------------------------------
__global__ __launch_bounds__(256) void k_out(const float* __restrict__ x,
        const float* __restrict__ bv, const float* __restrict__ gamma,
        float* __restrict__ out) {
    __shared__ uint32_t As[64*68];   // [c][m(64)+4]
    __shared__ uint32_t Bs[64*72];   // [m][n(64)+8]
    __shared__ float dens[64], kss[64];
    const int tid = threadIdx.x, w = tid>>5, lane = tid&31;
    const int gr = lane>>2, qt = lane&3;
    const int c0 = blockIdx.x*64, n0 = blockIdx.y*64, b = blockIdx.z;
    const int M0 = (w>>1)*16, N0 = (w&1)*32;

    if (tid < 64) kss[tid] = g_Ksum[b*DD + tid];
    #pragma unroll
    for (int i = 0; i < 4; i++) {     // A = sum_sp KV4 + bv*Ksum
        int id = tid + i*256, r = id>>4, m4 = id&15;
        const float* kvb = g_KV4 + ((size_t)b*CC + c0 + r)*DD + m4*4;
        float4 v  = *(const float4*)(kvb);
        float4 v1 = *(const float4*)(kvb + (size_t)SLAB);
        float4 v2 = *(const float4*)(kvb + (size_t)2*SLAB);
        float4 v3 = *(const float4*)(kvb + (size_t)3*SLAB);
        v.x += v1.x + v2.x + v3.x; v.y += v1.y + v2.y + v3.y;
        v.z += v1.z + v2.z + v3.z; v.w += v1.w + v2.w + v3.w;
        float4 k4 = *(const float4*)(g_Ksum + b*DD + m4*4);
        float bvc = __ldg(bv + c0 + r);
        v.x = fmaf(bvc, k4.x, v.x); v.y = fmaf(bvc, k4.y, v.y);
        v.z = fmaf(bvc, k4.z, v.z); v.w = fmaf(bvc, k4.w, v.w);
        uint32_t* p = &As[r*68 + m4*4];
        p[0]=tf(v.x); p[1]=tf(v.y); p[2]=tf(v.z); p[3]=tf(v.w);
    }
    #pragma unroll
    for (int i = 0; i < 4; i++) {     // B = phiQ [m][n]
        int id = tid + i*256, r = id>>4, n4 = id&15;
        float4 v = *(const float4*)(g_Q + ((size_t)b*DD + r)*NN + n0 + n4*4);
        uint32_t* p = &Bs[r*72 + n4*4];
        p[0]=tf(v.x); p[1]=tf(v.y); p[2]=tf(v.z); p[3]=tf(v.w);
    }
    __syncthreads();
    if (tid < 64) {                   // den[n] = sum_m phiQ*(Ksum+eps)
        float d = 0.f;
        #pragma unroll 16
        for (int m = 0; m < 64; m++)
            d = fmaf(__uint_as_float(Bs[m*72 + tid]), kss[m] + EPS, d);
        dens[tid] = d;
    }
    float acc[4][4];
    #pragma unroll
    for (int nt = 0; nt < 4; nt++)
        #pragma unroll
        for (int i = 0; i < 4; i++) acc[nt][i] = 0.f;
    #pragma unroll
    for (int k0 = 0; k0 < 64; k0 += 8) {
        uint32_t af[4], bf[4][2];
        int base = (M0 + gr)*68 + k0 + qt;
        af[0] = As[base];     af[1] = As[base + 8*68];
        af[2] = As[base + 4]; af[3] = As[base + 8*68 + 4];
        #pragma unroll
        for (int nt = 0; nt < 4; nt++) {
            int bb = (k0 + qt)*72 + N0 + 8*nt + gr;
            bf[nt][0] = Bs[bb]; bf[nt][1] = Bs[bb + 4*72];
        }
        #pragma unroll
        for (int nt = 0; nt < 4; nt++)
            MMA8(acc[nt], af, bf[nt][0], bf[nt][1]);
    }
    __syncthreads();
    const float gm = gamma[0];
    #pragma unroll
    for (int h = 0; h < 2; h++) {
        const int c = c0 + M0 + 8*h + gr;
        #pragma unroll
        for (int nt = 0; nt < 4; nt++) {
            const int nl = N0 + 8*nt + 2*qt;
            const float rn0 = gm / dens[nl], rn1 = gm / dens[nl+1];
            const size_t bi = ((size_t)b*CC + c)*NN + n0 + nl;
            float2 xv = *(const float2*)(x + bi);
            float2 o;
            o.x = fmaf(acc[nt][2*h],   rn0, xv.x);
            o.y = fmaf(acc[nt][2*h+1], rn1, xv.y);
            *(float2*)(out + bi) = o;
        }
    }
}

// ---------------------------------------------------------------------------
extern "C" void kernel_launch(void* const* d_in, const int* in_sizes, int n_in,
                              void* d_out, int out_size) {
    const float* x     = (const float*)d_in[0];
    const float* Wq    = (const float*)d_in[1];
    const float* bq    = (const float*)d_in[2];
    const float* Wk    = (const float*)d_in[3];
    const float* bk    = (const float*)d_in[4];
    const float* Wv    = (const float*)d_in[5];
    const float* bv    = (const float*)d_in[6];
    const float* gamma = (const float*)d_in[7];
    float* out = (float*)d_out;

    k_zero<<<1, 512>>>();
    k_qk  <<<dim3(NN/128, BB), 256>>>(x, Wq, bq, Wk, bk);
    k_kx  <<<dim3(CC/128, 16, BB), 256>>>(x);
    k_red <<<SLAB/256, 256>>>();
    k_kv  <<<dim3(CC/64, 4, BB), 256>>>(Wv);
    k_out <<<dim3(CC/64, NN/64, BB), 256>>>(x, bv, gamma, out);
}

// round 8
// speedup vs baseline: 1.1273x; 1.0659x over previous
#include <cuda_runtime.h>
#include <cstdint>

#define BB 8
#define CC 512
#define DD 64
#define NN 16384
#define PARAM 10.0f
#define EPS 1e-6f

__device__ float g_Q[BB*DD*NN];     // phi(Q) [b][m][n]
__device__ float g_Kt[BB*NN*DD];    // phi(K) transposed [b][n][m]
__device__ float g_Ksum[BB*DD];
__device__ float g_KXT[BB*CC*DD];   // (phiK @ x^T)^T [b][c][m]
__device__ float g_KVT[BB*CC*DD];   // KV^T (no bias) [b][c][m]

__device__ __forceinline__ float fmap(float t) {
    return t > 0.f ? fmaf(PARAM, t, 1.f) : __expf(PARAM * t);
}
__device__ __forceinline__ uint32_t tf(float x) {
    uint32_t u; asm("cvt.rna.tf32.f32 %0, %1;" : "=r"(u) : "f"(x)); return u;
}
#define MMA8(d, a, b0, b1) \
    asm volatile("mma.sync.aligned.m16n8k8.row.col.f32.tf32.tf32.f32 " \
        "{%0,%1,%2,%3}, {%4,%5,%6,%7}, {%8,%9}, {%0,%1,%2,%3};" \
        : "+f"((d)[0]), "+f"((d)[1]), "+f"((d)[2]), "+f"((d)[3]) \
        : "r"((a)[0]), "r"((a)[1]), "r"((a)[2]), "r"((a)[3]), "r"(b0), "r"(b1))

// ---------------------------------------------------------------------------
__global__ void k_zero() {
    int i = blockIdx.x*blockDim.x + threadIdx.x;
    if (i < BB*CC*DD) { g_KXT[i] = 0.f; g_KVT[i] = 0.f; }
    if (i < BB*DD) g_Ksum[i] = 0.f;
}

// ---------------------------------------------------------------------------
// k_qk: C[128m][128n] = [Wq;Wk](128x512) @ x_tile(512c x 128n). tf32 mma.
// Epilogue: bias+fmap; m<64 -> g_Q[m][n]; m>=64 -> g_Kt[n][m], Ksum atomics.
// ---------------------------------------------------------------------------
__global__ __launch_bounds__(256) void k_qk(const float* __restrict__ x,
        const float* __restrict__ Wq, const float* __restrict__ bq,
        const float* __restrict__ Wk, const float* __restrict__ bk) {
    __shared__ uint32_t As[128*36];   // [m][k(32)+4]
    __shared__ uint32_t Bs[32*136];   // [k(c)][n(128)+8]
    const int tid = threadIdx.x, w = tid>>5, lane = tid&31;
    const int gr = lane>>2, qt = lane&3;
    const int b = blockIdx.y, n0 = blockIdx.x*128;
    const int M0 = (w>>1)*32, N0 = (w&1)*64;
    const float* xb = x + (size_t)b*CC*NN;

    float4 pA[4], pB[4];
    #pragma unroll
    for (int i = 0; i < 4; i++) {
        int id = tid + i*256, r = id>>3, c4 = id&7;
        const float* Wr = r < 64 ? Wq + r*CC : Wk + (size_t)(r-64)*CC;
        pA[i] = *(const float4*)(Wr + c4*4);
    }
    #pragma unroll
    for (int i = 0; i < 4; i++) {
        int id = tid + i*256, r = id>>5, n4 = id&31;
        pB[i] = *(const float4*)(xb + (size_t)r*NN + n0 + n4*4);
    }
    float acc[2][8][4];
    #pragma unroll
    for (int mt = 0; mt < 2; mt++)
        #pragma unroll
        for (int nt = 0; nt < 8; nt++)
            #pragma unroll
            for (int i = 0; i < 4; i++) acc[mt][nt][i] = 0.f;

    for (int ci = 0; ci < 16; ci++) {
        #pragma unroll
        for (int i = 0; i < 4; i++) {
            int id = tid + i*256, r = id>>3, c4 = id&7;
            uint32_t* p = &As[r*36 + c4*4];
            p[0]=tf(pA[i].x); p[1]=tf(pA[i].y); p[2]=tf(pA[i].z); p[3]=tf(pA[i].w);
        }
        #pragma unroll
        for (int i = 0; i < 4; i++) {
            int id = tid + i*256, r = id>>5, n4 = id&31;
            uint32_t* p = &Bs[r*136 + n4*4];
            p[0]=tf(pB[i].x); p[1]=tf(pB[i].y); p[2]=tf(pB[i].z); p[3]=tf(pB[i].w);
        }
        __syncthreads();
        if (ci < 15) {
            int kc = (ci+1)*32;
            #pragma unroll
            for (int i = 0; i < 4; i++) {
                int id = tid + i*256, r = id>>3, c4 = id&7;
                const float* Wr = r < 64 ? Wq + r*CC : Wk + (size_t)(r-64)*CC;
                pA[i] = *(const float4*)(Wr + kc + c4*4);
            }
            #pragma unroll
            for (int i = 0; i < 4; i++) {
                int id = tid + i*256, r = id>>5, n4 = id&31;
                pB[i] = *(const float4*)(xb + (size_t)(kc+r)*NN + n0 + n4*4);
            }
        }
        #pragma unroll
        for (int k0 = 0; k0 < 32; k0 += 8) {
            uint32_t af[2][4], bf[8][2];
            #pragma unroll
            for (int mt = 0; mt < 2; mt++) {
                int base = (M0 + 16*mt + gr)*36 + k0 + qt;
                af[mt][0] = As[base];       af[mt][1] = As[base + 8*36];
                af[mt][2] = As[base + 4];   af[mt][3] = As[base + 8*36 + 4];
            }
            #pragma unroll
            for (int nt = 0; nt < 8; nt++) {
                int bb = (k0 + qt)*136 + N0 + 8*nt + gr;
                bf[nt][0] = Bs[bb]; bf[nt][1] = Bs[bb + 4*136];
            }
            #pragma unroll
            for (int mt = 0; mt < 2; mt++)
                #pragma unroll
                for (int nt = 0; nt < 8; nt++)
                    MMA8(acc[mt][nt], af[mt], bf[nt][0], bf[nt][1]);
        }
        __syncthreads();
    }

    #pragma unroll
    for (int mt = 0; mt < 2; mt++)
        #pragma unroll
        for (int h = 0; h < 2; h++) {
            const int m = M0 + 16*mt + 8*h + gr;
            const float bias = m < 64 ? __ldg(bq + m) : __ldg(bk + m - 64);
            float vv[8][2], ks = 0.f;
            #pragma unroll
            for (int nt = 0; nt < 8; nt++) {
                vv[nt][0] = fmap(acc[mt][nt][2*h]   + bias);
                vv[nt][1] = fmap(acc[mt][nt][2*h+1] + bias);
                ks += vv[nt][0] + vv[nt][1];
            }
            if (m < 64) {
                float* dst = g_Q + ((size_t)b*DD + m)*NN + n0 + N0;
                #pragma unroll
                for (int nt = 0; nt < 8; nt++)
                    *(float2*)(dst + 8*nt + 2*qt) = make_float2(vv[nt][0], vv[nt][1]);
            } else {
                const int mm = m - 64;
                #pragma unroll
                for (int nt = 0; nt < 8; nt++) {
                    int n = n0 + N0 + 8*nt + 2*qt;
                    float* dk = g_Kt + ((size_t)b*NN + n)*DD + mm;
                    dk[0] = vv[nt][0]; dk[DD] = vv[nt][1];
                }
                ks += __shfl_xor_sync(0xffffffffu, ks, 1);
                ks += __shfl_xor_sync(0xffffffffu, ks, 2);
                if (qt == 0) atomicAdd(&g_Ksum[b*DD + mm], ks);
            }
        }
}

// ---------------------------------------------------------------------------
// k_kx: KXT[128c][64m] += x_tile(c x n) @ phiK^T. A=x, B=g_Kt. Split-K=16,
// L2-resident atomics.
// ---------------------------------------------------------------------------
__global__ __launch_bounds__(256) void k_kx(const float* __restrict__ x) {
    __shared__ uint32_t As[128*36];   // [c][k(32)+4]
    __shared__ uint32_t Bs[32*72];    // [k(n)][m(64)+8]
    const int tid = threadIdx.x, w = tid>>5, lane = tid&31;
    const int gr = lane>>2, qt = lane&3;
    const int c0 = blockIdx.x*128, b = blockIdx.z;
    const int nbase = blockIdx.y*(NN/16);
    const int M0 = (w>>1)*32, N0 = (w&1)*32;

    float4 pA[4], pB[2];
    #pragma unroll
    for (int i = 0; i < 4; i++) {
        int id = tid + i*256, r = id>>3, n4 = id&7;
        pA[i] = *(const float4*)(x + ((size_t)(b*CC + c0 + r))*NN + nbase + n4*4);
    }
    #pragma unroll
    for (int i = 0; i < 2; i++) {
        int id = tid + i*256, r = id>>4, m4 = id&15;
        pB[i] = *(const float4*)(g_Kt + ((size_t)b*NN + nbase + r)*DD + m4*4);
    }
    float acc[2][4][4];
    #pragma unroll
    for (int mt = 0; mt < 2; mt++)
        #pragma unroll
        for (int nt = 0; nt < 4; nt++)
            #pragma unroll
            for (int i = 0; i < 4; i++) acc[mt][nt][i] = 0.f;

    for (int ci = 0; ci < (NN/16)/32; ci++) {
        #pragma unroll
        for (int i = 0; i < 4; i++) {
            int id = tid + i*256, r = id>>3, n4 = id&7;
            uint32_t* p = &As[r*36 + n4*4];
            p[0]=tf(pA[i].x); p[1]=tf(pA[i].y); p[2]=tf(pA[i].z); p[3]=tf(pA[i].w);
        }
        #pragma unroll
        for (int i = 0; i < 2; i++) {
            int id = tid + i*256, r = id>>4, m4 = id&15;
            uint32_t* p = &Bs[r*72 + m4*4];
            p[0]=tf(pB[i].x); p[1]=tf(pB[i].y); p[2]=tf(pB[i].z); p[3]=tf(pB[i].w);
        }
        __syncthreads();
        if (ci < (NN/16)/32 - 1) {
            int kn = nbase + (ci+1)*32;
            #pragma unroll
            for (int i = 0; i < 4; i++) {
                int id = tid + i*256, r = id>>3, n4 = id&7;
                pA[i] = *(const float4*)(x + ((size_t)(b*CC + c0 + r))*NN + kn + n4*4);
            }
            #pragma unroll
            for (int i = 0; i < 2; i++) {
                int id = tid + i*256, r = id>>4, m4 = id&15;
                pB[i] = *(const float4*)(g_Kt + ((size_t)b*NN + kn + r)*DD + m4*4);
            }
        }
        #pragma unroll
        for (int k0 = 0; k0 < 32; k0 += 8) {
            uint32_t af[2][4], bf[4][2];
            #pragma unroll
            for (int mt = 0; mt < 2; mt++) {
                int base = (M0 + 16*mt + gr)*36 + k0 + qt;
                af[mt][0] = As[base];     af[mt][1] = As[base + 8*36];
                af[mt][2] = As[base + 4]; af[mt][3] = As[base + 8*36 + 4];
            }
            #pragma unroll
            for (int nt = 0; nt < 4; nt++) {
                int bb = (k0 + qt)*72 + N0 + 8*nt + gr;
                bf[nt][0] = Bs[bb]; bf[nt][1] = Bs[bb + 4*72];
            }
            #pragma unroll
            for (int mt = 0; mt < 2; mt++)
                #pragma unroll
                for (int nt = 0; nt < 4; nt++)
                    MMA8(acc[mt][nt], af[mt], bf[nt][0], bf[nt][1]);
        }
        __syncthreads();
    }
    #pragma unroll
    for (int mt = 0; mt < 2; mt++)
        #pragma unroll
        for (int h = 0; h < 2; h++) {
            int c = c0 + M0 + 16*mt + 8*h + gr;
            #pragma unroll
            for (int nt = 0; nt < 4; nt++) {
                int m = N0 + 8*nt + 2*qt;
                float* d = g_KXT + ((size_t)b*CC + c)*DD + m;
                atomicAdd(d,     acc[mt][nt][2*h]);
                atomicAdd(d + 1, acc[mt][nt][2*h+1]);
            }
        }
}

// ---------------------------------------------------------------------------
// k_kv (SIMT, split-K=4): KVT[c][m] += sum_{c'} Wv[c][c'] * KXT[c'][m]
// ---------------------------------------------------------------------------
__global__ __launch_bounds__(256) void k_kv(const float* __restrict__ Wv) {
    __shared__ float Ws[64*36];   // [c][c'(32)+4]
    __shared__ float Xs[32*68];   // [c'][m(64)+4]
    const int c0 = blockIdx.x*64, sp = blockIdx.y, b = blockIdx.z;
    const int tid = threadIdx.x, tx = tid&15, ty = tid>>4;

    float acc[4][4] = {};
    for (int kk = 0; kk < 4; kk++) {
        const int cp0 = sp*128 + kk*32;
        #pragma unroll
        for (int i = 0; i < 2; i++) {
            int id = tid + i*256, r = id>>3, q4 = id&7;
            *(float4*)&Ws[r*36 + q4*4] =
                *(const float4*)(Wv + (size_t)(c0 + r)*CC + cp0 + q4*4);
        }
        #pragma unroll
        for (int i = 0; i < 2; i++) {
            int id = tid + i*256, r = id>>4, m4 = id&15;
            *(float4*)&Xs[r*68 + m4*4] =
                *(const float4*)(g_KXT + ((size_t)(b*CC) + cp0 + r)*DD + m4*4);
        }
        __syncthreads();
        #pragma unroll
        for (int k = 0; k < 32; k++) {
            float a[4], bb[4];
            #pragma unroll
            for (int i = 0; i < 4; i++) a[i] = Ws[(ty*4+i)*36 + k];
            #pragma unroll
            for (int j = 0; j < 4; j++) bb[j] = Xs[k*68 + tx*4 + j];
            #pragma unroll
            for (int i = 0; i < 4; i++)
                #pragma unroll
                for (int j = 0; j < 4; j++)
                    acc[i][j] = fmaf(a[i], bb[j], acc[i][j]);
        }
        __syncthreads();
    }
    #pragma unroll
    for (int i = 0; i < 4; i++)
        #pragma unroll
        for (int j = 0; j < 4; j++)
            atomicAdd(&g_KVT[((size_t)b*CC + c0 + ty*4+i)*DD + tx*4 + j], acc[i][j]);
}

// ---------------------------------------------------------------------------
// k_out: one block owns a 64-n stripe; loads phiQ tile ONCE, loops all 8
// c-chunks of 64. A = (KVT + bv*Ksum) (L2-resident). Fused den + residual.
// ---------------------------------------------------------------------------
__global__ __launch_bounds__(256) void k_out(const float* __restrict__ x,
        const float* __restrict__ bv, const float* __restrict__ gamma,
        float* __restrict__ out) {
    __shared__ uint32_t As[64*68];   // [c][m(64)+4]
    __shared__ uint32_t Bs[64*72];   // [m][n(64)+8]
    __shared__ float dens[64], kss[64];
    const int tid = threadIdx.x, w = tid>>5, lane = tid&31;
    const int gr = lane>>2, qt = lane&3;
    const int n0 = blockIdx.x*64, b = blockIdx.y;
    const int M0 = (w>>1)*16, N0 = (w&1)*32;

    if (tid < 64) kss[tid] = g_Ksum[b*DD + tid];
    #pragma unroll
    for (int i = 0; i < 4; i++) {     // B = phiQ [m][n], loaded once
        int id = tid + i*256, r = id>>4, n4 = id&15;
        float4 v = *(const float4*)(g_Q + ((size_t)b*DD + r)*NN + n0 + n4*4);
        uint32_t* p = &Bs[r*72 + n4*4];
        p[0]=tf(v.x); p[1]=tf(v.y); p[2]=tf(v.z); p[3]=tf(v.w);
    }
    __syncthreads();
    if (tid < 64) {                   // den[n] = sum_m phiQ*(Ksum+eps), once
        float d = 0.f;
        #pragma unroll 16
        for (int m = 0; m < 64; m++)
            d = fmaf(__uint_as_float(Bs[m*72 + tid]), kss[m] + EPS, d);
        dens[tid] = d;
    }
    const float gm = gamma[0];

    for (int c0 = 0; c0 < CC; c0 += 64) {
        #pragma unroll
        for (int i = 0; i < 4; i++) {     // A = KVT + bv*Ksum (L2-hot)
            int id = tid + i*256, r = id>>4, m4 = id&15;
            float4 v = *(const float4*)(g_KVT + ((size_t)b*CC + c0 + r)*DD + m4*4);
            float4 k4 = *(const float4*)(g_Ksum + b*DD + m4*4);
            float bvc = __ldg(bv + c0 + r);
            v.x = fmaf(bvc, k4.x, v.x); v.y = fmaf(bvc, k4.y, v.y);
            v.z = fmaf(bvc, k4.z, v.z); v.w = fmaf(bvc, k4.w, v.w);
            uint32_t* p = &As[r*68 + m4*4];
            p[0]=tf(v.x); p[1]=tf(v.y); p[2]=tf(v.z); p[3]=tf(v.w);
        }
        __syncthreads();   // As ready (also covers dens on first iteration)

        float acc[4][4];
        #pragma unroll
        for (int nt = 0; nt < 4; nt++)
            #pragma unroll
            for (int i = 0; i < 4; i++) acc[nt][i] = 0.f;
        #pragma unroll
        for (int k0 = 0; k0 < 64; k0 += 8) {
            uint32_t af[4], bf[4][2];
            int base = (M0 + gr)*68 + k0 + qt;
            af[0] = As[base];     af[1] = As[base + 8*68];
            af[2] = As[base + 4]; af[3] = As[base + 8*68 + 4];
            #pragma unroll
            for (int nt = 0; nt < 4; nt++) {
                int bb = (k0 + qt)*72 + N0 + 8*nt + gr;
                bf[nt][0] = Bs[bb]; bf[nt][1] = Bs[bb + 4*72];
            }
            #pragma unroll
            for (int nt = 0; nt < 4; nt++)
                MMA8(acc[nt], af, bf[nt][0], bf[nt][1]);
        }
        #pragma unroll
        for (int h = 0; h < 2; h++) {
            const int c = c0 + M0 + 8*h + gr;
            #pragma unroll
            for (int nt = 0; nt < 4; nt++) {
                const int nl = N0 + 8*nt + 2*qt;
                const float rn0 = gm / dens[nl], rn1 = gm / dens[nl+1];
                const size_t bi = ((size_t)b*CC + c)*NN + n0 + nl;
                float2 xv = *(const float2*)(x + bi);
                float2 o;
                o.x = fmaf(acc[nt][2*h],   rn0, xv.x);
                o.y = fmaf(acc[nt][2*h+1], rn1, xv.y);
                *(float2*)(out + bi) = o;
            }
        }
        __syncthreads();   // all reads of As done before next overwrite
    }
}

// ---------------------------------------------------------------------------
extern "C" void kernel_launch(void* const* d_in, const int* in_sizes, int n_in,
                              void* d_out, int out_size) {
    const float* x     = (const float*)d_in[0];
    const float* Wq    = (const float*)d_in[1];
    const float* bq    = (const float*)d_in[2];
    const float* Wk    = (const float*)d_in[3];
    const float* bk    = (const float*)d_in[4];
    const float* Wv    = (const float*)d_in[5];
    const float* bv    = (const float*)d_in[6];
    const float* gamma = (const float*)d_in[7];
    float* out = (float*)d_out;

    k_zero<<<512, 512>>>();
    k_qk  <<<dim3(NN/128, BB), 256>>>(x, Wq, bq, Wk, bk);
    k_kx  <<<dim3(CC/128, 16, BB), 256>>>(x);
    k_kv  <<<dim3(CC/64, 4, BB), 256>>>(Wv);
    k_out <<<dim3(NN/64, BB), 256>>>(x, bv, gamma, out);
}